// round 4
// baseline (speedup 1.0000x reference)
#include <cuda_runtime.h>

#define Bsz 128
#define Isz 32
#define Lsz 96
#define Hsz 512
#define Fsz 24
#define Ssz 16
#define NSTEPS 23
#define SB 2048          // S*B
#define G3H 1536         // 3*H

// ---------------- scratch (device globals; no allocation allowed) ----------
__device__ float g_xs[Lsz * Bsz * Isz];          // x transposed to [L*B, I]
__device__ float g_gi[(size_t)Lsz * Bsz * G3H];  // encoder input gates, all steps
__device__ float g_gh[(size_t)SB * G3H];         // recurrent gates scratch
__device__ float g_hA[Bsz * Hsz];                // encoder hidden
__device__ float g_h[SB * Hsz];                  // SDE/decoder hidden
__device__ float g_a1[SB * Hsz];                 // tanh(h W1^T + b1)
__device__ float g_gv[SB * Hsz];                 // softplus diffusion

// ---------------- small utility kernels ----------------
__global__ __launch_bounds__(256) void zero_kernel(float* p, int n) {
    int i = blockIdx.x * blockDim.x + threadIdx.x;
    if (i < n) p[i] = 0.f;
}

// xs[(l*B+b)*I + i] = x[(b*I+i)*L + l]
__global__ __launch_bounds__(256) void transpose_x(const float* __restrict__ x,
                                                   float* __restrict__ xs) {
    int o = blockIdx.x * blockDim.x + threadIdx.x;
    if (o >= Lsz * Bsz * Isz) return;
    int i = o & 31;
    int b = (o >> 5) & 127;
    int l = o >> 12;
    xs[o] = x[(b * Isz + i) * Lsz + l];
}

// h_sde[s*B+b, n] = h_enc[b, n]
__global__ __launch_bounds__(256) void bcast_kernel(const float* __restrict__ src,
                                                    float* __restrict__ dst) {
    int idx = blockIdx.x * blockDim.x + threadIdx.x;
    if (idx >= SB * Hsz) return;
    int m = idx >> 9;
    int j = idx & 511;
    dst[idx] = src[(m & 127) * Hsz + j];
}

// ---------------- fused GEMM epilogues ----------------
// MODE 0: C = acc + bias
// MODE 1: C = tanh(acc + bias)
// MODE 2: C = softplus(acc + bias)
// MODE 3: C = h + dt*(acc+bias) + g * (noise*sqrt(dt))   (Euler-Maruyama)
template <int MODE>
__device__ __forceinline__ void epi_store(float val, int m, int n, int N,
                                          float* __restrict__ C,
                                          const float* __restrict__ hb,
                                          const float* __restrict__ gb,
                                          const float* __restrict__ nz, int t) {
    size_t ci = (size_t)m * N + n;
    if (MODE == 0) {
        C[ci] = val;
    } else if (MODE == 1) {
        C[ci] = tanhf(val);
    } else if (MODE == 2) {
        C[ci] = (val > 0.f) ? val + log1pf(expf(-val)) : log1pf(expf(val));
    } else {
        const float dtv = 24.0f / 23.0f;
        const float sq  = sqrtf(24.0f / 23.0f);
        int s = m >> 7;          // m = s*128 + b
        int b = m & 127;
        float dw = nz[(((size_t)s * NSTEPS + t) * Bsz + b) * Hsz + n] * sq;
        C[ci] = hb[ci] + dtv * val + gb[ci] * dw;
    }
}

// C[M,N] = epi(A[M,K] @ W[N,K]^T + bias).  Tiles 64x64x16, 256 threads, 4x4/thread.
// Requires M%64==0, N%64==0, K%16==0.
template <int MODE>
__global__ __launch_bounds__(256) void gemm64(const float* __restrict__ A,
                                              const float* __restrict__ W,
                                              const float* __restrict__ bias,
                                              float* __restrict__ C, int K, int N,
                                              const float* __restrict__ hb,
                                              const float* __restrict__ gb,
                                              const float* __restrict__ nz, int t) {
    __shared__ float As[16][68];
    __shared__ float Ws[16][68];
    const int bm = blockIdx.y * 64, bn = blockIdx.x * 64;
    const int tid = threadIdx.x;
    const int lr = tid >> 2;
    const int lk = (tid & 3) << 2;
    const int tm = (tid >> 4) << 2;
    const int tn = (tid & 15) << 2;
    float acc[4][4];
#pragma unroll
    for (int u = 0; u < 4; u++)
#pragma unroll
        for (int v = 0; v < 4; v++) acc[u][v] = 0.f;

    const float* Ap = A + (size_t)(bm + lr) * K + lk;
    const float* Wp = W + (size_t)(bn + lr) * K + lk;
    for (int k0 = 0; k0 < K; k0 += 16) {
        float4 av = *(const float4*)(Ap + k0);
        float4 wv = *(const float4*)(Wp + k0);
        As[lk + 0][lr] = av.x; As[lk + 1][lr] = av.y;
        As[lk + 2][lr] = av.z; As[lk + 3][lr] = av.w;
        Ws[lk + 0][lr] = wv.x; Ws[lk + 1][lr] = wv.y;
        Ws[lk + 2][lr] = wv.z; Ws[lk + 3][lr] = wv.w;
        __syncthreads();
#pragma unroll
        for (int kk = 0; kk < 16; kk++) {
            float a0 = As[kk][tm + 0], a1 = As[kk][tm + 1];
            float a2 = As[kk][tm + 2], a3 = As[kk][tm + 3];
            float b0 = Ws[kk][tn + 0], b1 = Ws[kk][tn + 1];
            float b2 = Ws[kk][tn + 2], b3 = Ws[kk][tn + 3];
            acc[0][0] += a0 * b0; acc[0][1] += a0 * b1; acc[0][2] += a0 * b2; acc[0][3] += a0 * b3;
            acc[1][0] += a1 * b0; acc[1][1] += a1 * b1; acc[1][2] += a1 * b2; acc[1][3] += a1 * b3;
            acc[2][0] += a2 * b0; acc[2][1] += a2 * b1; acc[2][2] += a2 * b2; acc[2][3] += a2 * b3;
            acc[3][0] += a3 * b0; acc[3][1] += a3 * b1; acc[3][2] += a3 * b2; acc[3][3] += a3 * b3;
        }
        __syncthreads();
    }
#pragma unroll
    for (int u = 0; u < 4; u++) {
        int m = bm + tm + u;
#pragma unroll
        for (int v = 0; v < 4; v++) {
            int n = bn + tn + v;
            epi_store<MODE>(acc[u][v] + bias[n], m, n, N, C, hb, gb, nz, t);
        }
    }
}

// Small-M variant: tiles 32x64x16 (for the M=128 encoder recurrence -> 96 CTAs).
template <int MODE>
__global__ __launch_bounds__(256) void gemm32(const float* __restrict__ A,
                                              const float* __restrict__ W,
                                              const float* __restrict__ bias,
                                              float* __restrict__ C, int K, int N,
                                              const float* __restrict__ hb,
                                              const float* __restrict__ gb,
                                              const float* __restrict__ nz, int t) {
    __shared__ float As[16][36];
    __shared__ float Ws[16][68];
    const int bm = blockIdx.y * 32, bn = blockIdx.x * 64;
    const int tid = threadIdx.x;
    const int lr = tid >> 2;
    const int lk = (tid & 3) << 2;
    const int tm = (tid >> 4) << 1;
    const int tn = (tid & 15) << 2;
    float acc[2][4];
#pragma unroll
    for (int u = 0; u < 2; u++)
#pragma unroll
        for (int v = 0; v < 4; v++) acc[u][v] = 0.f;

    const float* Ap = A + (size_t)(bm + lr) * K + lk;   // valid for tid<128
    const float* Wp = W + (size_t)(bn + lr) * K + lk;
    for (int k0 = 0; k0 < K; k0 += 16) {
        if (tid < 128) {
            float4 av = *(const float4*)(Ap + k0);
            As[lk + 0][lr] = av.x; As[lk + 1][lr] = av.y;
            As[lk + 2][lr] = av.z; As[lk + 3][lr] = av.w;
        }
        float4 wv = *(const float4*)(Wp + k0);
        Ws[lk + 0][lr] = wv.x; Ws[lk + 1][lr] = wv.y;
        Ws[lk + 2][lr] = wv.z; Ws[lk + 3][lr] = wv.w;
        __syncthreads();
#pragma unroll
        for (int kk = 0; kk < 16; kk++) {
            float a0 = As[kk][tm + 0], a1 = As[kk][tm + 1];
            float b0 = Ws[kk][tn + 0], b1 = Ws[kk][tn + 1];
            float b2 = Ws[kk][tn + 2], b3 = Ws[kk][tn + 3];
            acc[0][0] += a0 * b0; acc[0][1] += a0 * b1; acc[0][2] += a0 * b2; acc[0][3] += a0 * b3;
            acc[1][0] += a1 * b0; acc[1][1] += a1 * b1; acc[1][2] += a1 * b2; acc[1][3] += a1 * b3;
        }
        __syncthreads();
    }
#pragma unroll
    for (int u = 0; u < 2; u++) {
        int m = bm + tm + u;
#pragma unroll
        for (int v = 0; v < 4; v++) {
            int n = bn + tn + v;
            epi_store<MODE>(acc[u][v] + bias[n], m, n, N, C, hb, gb, nz, t);
        }
    }
}

// GRU pointwise: h = (1-z)*n + z*h, in place. gi is [M,3H] (encoder) or [3H] (decoder).
template <bool GIVEC>
__global__ __launch_bounds__(256) void gru_combine(const float* __restrict__ gi,
                                                   const float* __restrict__ gh,
                                                   float* __restrict__ h, int M) {
    int idx = blockIdx.x * blockDim.x + threadIdx.x;
    if (idx >= M * Hsz) return;
    int m = idx >> 9;
    int j = idx & 511;
    float gir, giz, gin;
    if (GIVEC) {
        gir = gi[j]; giz = gi[Hsz + j]; gin = gi[2 * Hsz + j];
    } else {
        const float* p = gi + (size_t)m * G3H;
        gir = p[j]; giz = p[Hsz + j]; gin = p[2 * Hsz + j];
    }
    const float* q = gh + (size_t)m * G3H;
    float r = 1.f / (1.f + expf(-(gir + q[j])));
    float z = 1.f / (1.f + expf(-(giz + q[Hsz + j])));
    float n = tanhf(gin + r * q[2 * Hsz + j]);
    h[idx] = (1.f - z) * n + z * h[idx];
}

// out[(m*I+i)*F + f] = h[m,:] . out_W[i,:] + out_b[i].  8 rows/block, 256 blocks.
__global__ __launch_bounds__(256) void outproj(const float* __restrict__ h,
                                               const float* __restrict__ W,
                                               const float* __restrict__ bias,
                                               float* __restrict__ out, int f) {
    __shared__ float hs[8][Hsz];
    __shared__ float Ws[64][33];
    const int tid = threadIdx.x;
    const int m0 = blockIdx.x * 8;
    for (int idx = tid; idx < 8 * Hsz; idx += 256)
        hs[idx >> 9][idx & 511] = h[(size_t)(m0 + (idx >> 9)) * Hsz + (idx & 511)];
    const int r = tid >> 5, i = tid & 31;
    float acc = 0.f;
    for (int k0 = 0; k0 < Hsz; k0 += 64) {
        __syncthreads();
#pragma unroll
        for (int q = 0; q < 2; q++) {
            int fid = tid + q * 256;          // 0..511
            int i_ld = fid >> 4, c = fid & 15;
            float4 wv = *(const float4*)(W + (size_t)i_ld * Hsz + k0 + c * 4);
            Ws[c * 4 + 0][i_ld] = wv.x; Ws[c * 4 + 1][i_ld] = wv.y;
            Ws[c * 4 + 2][i_ld] = wv.z; Ws[c * 4 + 3][i_ld] = wv.w;
        }
        __syncthreads();
#pragma unroll 16
        for (int kk = 0; kk < 64; kk++) acc += hs[r][k0 + kk] * Ws[kk][i];
    }
    out[((size_t)(m0 + r) * Isz + i) * Fsz + f] = acc + bias[i];
}

// ---------------- launcher ----------------
extern "C" void kernel_launch(void* const* d_in, const int* in_sizes, int n_in,
                              void* d_out, int out_size) {
    const float* x        = (const float*)d_in[0];
    const float* noise    = (const float*)d_in[1];
    const float* enc_Wih  = (const float*)d_in[2];
    const float* enc_Whh  = (const float*)d_in[3];
    const float* enc_bih  = (const float*)d_in[4];
    const float* enc_bhh  = (const float*)d_in[5];
    const float* f_W1     = (const float*)d_in[6];
    const float* f_b1     = (const float*)d_in[7];
    const float* f_W2     = (const float*)d_in[8];
    const float* f_b2     = (const float*)d_in[9];
    const float* g_W      = (const float*)d_in[10];
    const float* g_b      = (const float*)d_in[11];
    // d_in[12] = dec_Wih (unused: decoder input is zero)
    const float* dec_Whh  = (const float*)d_in[13];
    const float* dec_bih  = (const float*)d_in[14];
    const float* dec_bhh  = (const float*)d_in[15];
    const float* out_W    = (const float*)d_in[16];
    const float* out_b    = (const float*)d_in[17];
    float* out = (float*)d_out;

    float *xs, *gi, *gh, *hA, *h, *a1, *gv;
    cudaGetSymbolAddress((void**)&xs, g_xs);
    cudaGetSymbolAddress((void**)&gi, g_gi);
    cudaGetSymbolAddress((void**)&gh, g_gh);
    cudaGetSymbolAddress((void**)&hA, g_hA);
    cudaGetSymbolAddress((void**)&h,  g_h);
    cudaGetSymbolAddress((void**)&a1, g_a1);
    cudaGetSymbolAddress((void**)&gv, g_gv);

    // ---- encoder ----
    zero_kernel<<<(Bsz * Hsz + 255) / 256, 256>>>(hA, Bsz * Hsz);
    transpose_x<<<(Lsz * Bsz * Isz + 255) / 256, 256>>>(x, xs);
    // gi_all = xs @ enc_Wih^T + enc_bih : [L*B, 3H], K=32
    gemm64<0><<<dim3(G3H / 64, (Lsz * Bsz) / 64), 256>>>(
        xs, enc_Wih, enc_bih, gi, Isz, G3H, nullptr, nullptr, nullptr, 0);
    for (int l = 0; l < Lsz; l++) {
        gemm32<0><<<dim3(G3H / 64, Bsz / 32), 256>>>(
            hA, enc_Whh, enc_bhh, gh, Hsz, G3H, nullptr, nullptr, nullptr, 0);
        gru_combine<false><<<(Bsz * Hsz + 255) / 256, 256>>>(
            gi + (size_t)l * Bsz * G3H, gh, hA, Bsz);
    }

    // ---- broadcast to S samples ----
    bcast_kernel<<<(SB * Hsz + 255) / 256, 256>>>(hA, h);

    // ---- Euler-Maruyama SDE ----
    for (int t = 0; t < NSTEPS; t++) {
        gemm64<1><<<dim3(Hsz / 64, SB / 64), 256>>>(
            h, f_W1, f_b1, a1, Hsz, Hsz, nullptr, nullptr, nullptr, 0);
        gemm64<2><<<dim3(Hsz / 64, SB / 64), 256>>>(
            h, g_W, g_b, gv, Hsz, Hsz, nullptr, nullptr, nullptr, 0);
        gemm64<3><<<dim3(Hsz / 64, SB / 64), 256>>>(
            a1, f_W2, f_b2, h, Hsz, Hsz, h, gv, noise, t);
    }

    // ---- decoder + output projection ----
    for (int f = 0; f < Fsz; f++) {
        gemm64<0><<<dim3(G3H / 64, SB / 64), 256>>>(
            h, dec_Whh, dec_bhh, gh, Hsz, G3H, nullptr, nullptr, nullptr, 0);
        gru_combine<true><<<(SB * Hsz + 255) / 256, 256>>>(dec_bih, gh, h, SB);
        outproj<<<SB / 8, 256>>>(h, out_W, out_b, out, f);
    }
}

// round 9
// speedup vs baseline: 1.0029x; 1.0029x over previous
#include <cuda_runtime.h>

#define Bsz 128
#define Isz 32
#define Lsz 96
#define Hsz 512
#define Fsz 24
#define Ssz 16
#define NSTEPS 23
#define SB 2048          // S*B
#define G3H 1536         // 3*H

// ---------------- scratch (device globals; no allocation allowed) ----------
__device__ float g_xs[Lsz * Bsz * Isz];          // x transposed to [L*B, I]
__device__ float g_gi[(size_t)Lsz * Bsz * G3H];  // encoder input gates, all steps
__device__ float g_gh[(size_t)SB * G3H];         // recurrent gates scratch
__device__ float g_hA[Bsz * Hsz];                // encoder hidden
__device__ float g_h[SB * Hsz];                  // SDE/decoder hidden
__device__ float g_a1[SB * Hsz];                 // tanh(h W1^T + b1)
__device__ float g_gv[SB * Hsz];                 // softplus diffusion

// ---------------- small utility kernels ----------------
__global__ __launch_bounds__(256) void zero_kernel(float* p, int n) {
    int i = blockIdx.x * blockDim.x + threadIdx.x;
    if (i < n) p[i] = 0.f;
}

// xs[(l*B+b)*I + i] = x[(b*I+i)*L + l]
__global__ __launch_bounds__(256) void transpose_x(const float* __restrict__ x,
                                                   float* __restrict__ xs) {
    int o = blockIdx.x * blockDim.x + threadIdx.x;
    if (o >= Lsz * Bsz * Isz) return;
    int i = o & 31;
    int b = (o >> 5) & 127;
    int l = o >> 12;
    xs[o] = x[(b * Isz + i) * Lsz + l];
}

// h_sde[s*B+b, n] = h_enc[b, n]
__global__ __launch_bounds__(256) void bcast_kernel(const float* __restrict__ src,
                                                    float* __restrict__ dst) {
    int idx = blockIdx.x * blockDim.x + threadIdx.x;
    if (idx >= SB * Hsz) return;
    int m = idx >> 9;
    int j = idx & 511;
    dst[idx] = src[(m & 127) * Hsz + j];
}

// ---------------- fused GEMM epilogues ----------------
// MODE 0: C = acc + bias
// MODE 1: C = tanh(acc + bias)
// MODE 2: C = softplus(acc + bias)
// MODE 3: C = h + dt*(acc+bias) + g * (noise*sqrt(dt))   (Euler-Maruyama)
template <int MODE>
__device__ __forceinline__ void epi_store(float val, int m, int n, int N,
                                          float* __restrict__ C,
                                          const float* __restrict__ hb,
                                          const float* __restrict__ gb,
                                          const float* __restrict__ nz, int t) {
    size_t ci = (size_t)m * N + n;
    if (MODE == 0) {
        C[ci] = val;
    } else if (MODE == 1) {
        C[ci] = tanhf(val);
    } else if (MODE == 2) {
        C[ci] = (val > 0.f) ? val + log1pf(expf(-val)) : log1pf(expf(val));
    } else {
        const float dtv = 24.0f / 23.0f;
        const float sq  = sqrtf(24.0f / 23.0f);
        int s = m >> 7;          // m = s*128 + b
        int b = m & 127;
        float dw = nz[(((size_t)s * NSTEPS + t) * Bsz + b) * Hsz + n] * sq;
        C[ci] = hb[ci] + dtv * val + gb[ci] * dw;
    }
}

// C[M,N] = epi(A[M,K] @ W[N,K]^T + bias).  Tiles 64x64x16, 256 threads, 4x4/thread.
// Requires M%64==0, N%64==0, K%16==0.
template <int MODE>
__global__ __launch_bounds__(256) void gemm64(const float* __restrict__ A,
                                              const float* __restrict__ W,
                                              const float* __restrict__ bias,
                                              float* __restrict__ C, int K, int N,
                                              const float* __restrict__ hb,
                                              const float* __restrict__ gb,
                                              const float* __restrict__ nz, int t) {
    __shared__ float As[16][68];
    __shared__ float Ws[16][68];
    const int bm = blockIdx.y * 64, bn = blockIdx.x * 64;
    const int tid = threadIdx.x;
    const int lr = tid >> 2;
    const int lk = (tid & 3) << 2;
    const int tm = (tid >> 4) << 2;
    const int tn = (tid & 15) << 2;
    float acc[4][4];
#pragma unroll
    for (int u = 0; u < 4; u++)
#pragma unroll
        for (int v = 0; v < 4; v++) acc[u][v] = 0.f;

    const float* Ap = A + (size_t)(bm + lr) * K + lk;
    const float* Wp = W + (size_t)(bn + lr) * K + lk;
    for (int k0 = 0; k0 < K; k0 += 16) {
        float4 av = *(const float4*)(Ap + k0);
        float4 wv = *(const float4*)(Wp + k0);
        As[lk + 0][lr] = av.x; As[lk + 1][lr] = av.y;
        As[lk + 2][lr] = av.z; As[lk + 3][lr] = av.w;
        Ws[lk + 0][lr] = wv.x; Ws[lk + 1][lr] = wv.y;
        Ws[lk + 2][lr] = wv.z; Ws[lk + 3][lr] = wv.w;
        __syncthreads();
#pragma unroll
        for (int kk = 0; kk < 16; kk++) {
            float a0 = As[kk][tm + 0], a1 = As[kk][tm + 1];
            float a2 = As[kk][tm + 2], a3 = As[kk][tm + 3];
            float b0 = Ws[kk][tn + 0], b1 = Ws[kk][tn + 1];
            float b2 = Ws[kk][tn + 2], b3 = Ws[kk][tn + 3];
            acc[0][0] += a0 * b0; acc[0][1] += a0 * b1; acc[0][2] += a0 * b2; acc[0][3] += a0 * b3;
            acc[1][0] += a1 * b0; acc[1][1] += a1 * b1; acc[1][2] += a1 * b2; acc[1][3] += a1 * b3;
            acc[2][0] += a2 * b0; acc[2][1] += a2 * b1; acc[2][2] += a2 * b2; acc[2][3] += a2 * b3;
            acc[3][0] += a3 * b0; acc[3][1] += a3 * b1; acc[3][2] += a3 * b2; acc[3][3] += a3 * b3;
        }
        __syncthreads();
    }
#pragma unroll
    for (int u = 0; u < 4; u++) {
        int m = bm + tm + u;
#pragma unroll
        for (int v = 0; v < 4; v++) {
            int n = bn + tn + v;
            epi_store<MODE>(acc[u][v] + bias[n], m, n, N, C, hb, gb, nz, t);
        }
    }
}

// Small-M variant: tiles 32x64x16 (for the M=128 encoder recurrence -> 96 CTAs).
template <int MODE>
__global__ __launch_bounds__(256) void gemm32(const float* __restrict__ A,
                                              const float* __restrict__ W,
                                              const float* __restrict__ bias,
                                              float* __restrict__ C, int K, int N,
                                              const float* __restrict__ hb,
                                              const float* __restrict__ gb,
                                              const float* __restrict__ nz, int t) {
    __shared__ float As[16][36];
    __shared__ float Ws[16][68];
    const int bm = blockIdx.y * 32, bn = blockIdx.x * 64;
    const int tid = threadIdx.x;
    const int lr = tid >> 2;
    const int lk = (tid & 3) << 2;
    const int tm = (tid >> 4) << 1;
    const int tn = (tid & 15) << 2;
    float acc[2][4];
#pragma unroll
    for (int u = 0; u < 2; u++)
#pragma unroll
        for (int v = 0; v < 4; v++) acc[u][v] = 0.f;

    const float* Ap = A + (size_t)(bm + lr) * K + lk;   // valid for tid<128
    const float* Wp = W + (size_t)(bn + lr) * K + lk;
    for (int k0 = 0; k0 < K; k0 += 16) {
        if (tid < 128) {
            float4 av = *(const float4*)(Ap + k0);
            As[lk + 0][lr] = av.x; As[lk + 1][lr] = av.y;
            As[lk + 2][lr] = av.z; As[lk + 3][lr] = av.w;
        }
        float4 wv = *(const float4*)(Wp + k0);
        Ws[lk + 0][lr] = wv.x; Ws[lk + 1][lr] = wv.y;
        Ws[lk + 2][lr] = wv.z; Ws[lk + 3][lr] = wv.w;
        __syncthreads();
#pragma unroll
        for (int kk = 0; kk < 16; kk++) {
            float a0 = As[kk][tm + 0], a1 = As[kk][tm + 1];
            float b0 = Ws[kk][tn + 0], b1 = Ws[kk][tn + 1];
            float b2 = Ws[kk][tn + 2], b3 = Ws[kk][tn + 3];
            acc[0][0] += a0 * b0; acc[0][1] += a0 * b1; acc[0][2] += a0 * b2; acc[0][3] += a0 * b3;
            acc[1][0] += a1 * b0; acc[1][1] += a1 * b1; acc[1][2] += a1 * b2; acc[1][3] += a1 * b3;
        }
        __syncthreads();
    }
#pragma unroll
    for (int u = 0; u < 2; u++) {
        int m = bm + tm + u;
#pragma unroll
        for (int v = 0; v < 4; v++) {
            int n = bn + tn + v;
            epi_store<MODE>(acc[u][v] + bias[n], m, n, N, C, hb, gb, nz, t);
        }
    }
}

// GRU pointwise: h = (1-z)*n + z*h, in place. gi is [M,3H] (encoder) or [3H] (decoder).
template <bool GIVEC>
__global__ __launch_bounds__(256) void gru_combine(const float* __restrict__ gi,
                                                   const float* __restrict__ gh,
                                                   float* __restrict__ h, int M) {
    int idx = blockIdx.x * blockDim.x + threadIdx.x;
    if (idx >= M * Hsz) return;
    int m = idx >> 9;
    int j = idx & 511;
    float gir, giz, gin;
    if (GIVEC) {
        gir = gi[j]; giz = gi[Hsz + j]; gin = gi[2 * Hsz + j];
    } else {
        const float* p = gi + (size_t)m * G3H;
        gir = p[j]; giz = p[Hsz + j]; gin = p[2 * Hsz + j];
    }
    const float* q = gh + (size_t)m * G3H;
    float r = 1.f / (1.f + expf(-(gir + q[j])));
    float z = 1.f / (1.f + expf(-(giz + q[Hsz + j])));
    float n = tanhf(gin + r * q[2 * Hsz + j]);
    h[idx] = (1.f - z) * n + z * h[idx];
}

// out[(m*I+i)*F + f] = h[m,:] . out_W[i,:] + out_b[i].  8 rows/block, 256 blocks.
__global__ __launch_bounds__(256) void outproj(const float* __restrict__ h,
                                               const float* __restrict__ W,
                                               const float* __restrict__ bias,
                                               float* __restrict__ out, int f) {
    __shared__ float hs[8][Hsz];
    __shared__ float Ws[64][33];
    const int tid = threadIdx.x;
    const int m0 = blockIdx.x * 8;
    for (int idx = tid; idx < 8 * Hsz; idx += 256)
        hs[idx >> 9][idx & 511] = h[(size_t)(m0 + (idx >> 9)) * Hsz + (idx & 511)];
    const int r = tid >> 5, i = tid & 31;
    float acc = 0.f;
    for (int k0 = 0; k0 < Hsz; k0 += 64) {
        __syncthreads();
#pragma unroll
        for (int q = 0; q < 2; q++) {
            int fid = tid + q * 256;          // 0..511
            int i_ld = fid >> 4, c = fid & 15;
            float4 wv = *(const float4*)(W + (size_t)i_ld * Hsz + k0 + c * 4);
            Ws[c * 4 + 0][i_ld] = wv.x; Ws[c * 4 + 1][i_ld] = wv.y;
            Ws[c * 4 + 2][i_ld] = wv.z; Ws[c * 4 + 3][i_ld] = wv.w;
        }
        __syncthreads();
#pragma unroll 16
        for (int kk = 0; kk < 64; kk++) acc += hs[r][k0 + kk] * Ws[kk][i];
    }
    out[((size_t)(m0 + r) * Isz + i) * Fsz + f] = acc + bias[i];
}

// ---------------- launcher ----------------
extern "C" void kernel_launch(void* const* d_in, const int* in_sizes, int n_in,
                              void* d_out, int out_size) {
    const float* x        = (const float*)d_in[0];
    const float* noise    = (const float*)d_in[1];
    const float* enc_Wih  = (const float*)d_in[2];
    const float* enc_Whh  = (const float*)d_in[3];
    const float* enc_bih  = (const float*)d_in[4];
    const float* enc_bhh  = (const float*)d_in[5];
    const float* f_W1     = (const float*)d_in[6];
    const float* f_b1     = (const float*)d_in[7];
    const float* f_W2     = (const float*)d_in[8];
    const float* f_b2     = (const float*)d_in[9];
    const float* g_W      = (const float*)d_in[10];
    const float* g_b      = (const float*)d_in[11];
    // d_in[12] = dec_Wih (unused: decoder input is zero)
    const float* dec_Whh  = (const float*)d_in[13];
    const float* dec_bih  = (const float*)d_in[14];
    const float* dec_bhh  = (const float*)d_in[15];
    const float* out_W    = (const float*)d_in[16];
    const float* out_b    = (const float*)d_in[17];
    float* out = (float*)d_out;

    float *xs, *gi, *gh, *hA, *h, *a1, *gv;
    cudaGetSymbolAddress((void**)&xs, g_xs);
    cudaGetSymbolAddress((void**)&gi, g_gi);
    cudaGetSymbolAddress((void**)&gh, g_gh);
    cudaGetSymbolAddress((void**)&hA, g_hA);
    cudaGetSymbolAddress((void**)&h,  g_h);
    cudaGetSymbolAddress((void**)&a1, g_a1);
    cudaGetSymbolAddress((void**)&gv, g_gv);

    // ---- encoder ----
    zero_kernel<<<(Bsz * Hsz + 255) / 256, 256>>>(hA, Bsz * Hsz);
    transpose_x<<<(Lsz * Bsz * Isz + 255) / 256, 256>>>(x, xs);
    // gi_all = xs @ enc_Wih^T + enc_bih : [L*B, 3H], K=32
    gemm64<0><<<dim3(G3H / 64, (Lsz * Bsz) / 64), 256>>>(
        xs, enc_Wih, enc_bih, gi, Isz, G3H, nullptr, nullptr, nullptr, 0);
    for (int l = 0; l < Lsz; l++) {
        gemm32<0><<<dim3(G3H / 64, Bsz / 32), 256>>>(
            hA, enc_Whh, enc_bhh, gh, Hsz, G3H, nullptr, nullptr, nullptr, 0);
        gru_combine<false><<<(Bsz * Hsz + 255) / 256, 256>>>(
            gi + (size_t)l * Bsz * G3H, gh, hA, Bsz);
    }

    // ---- broadcast to S samples ----
    bcast_kernel<<<(SB * Hsz + 255) / 256, 256>>>(hA, h);

    // ---- Euler-Maruyama SDE ----
    for (int t = 0; t < NSTEPS; t++) {
        gemm64<1><<<dim3(Hsz / 64, SB / 64), 256>>>(
            h, f_W1, f_b1, a1, Hsz, Hsz, nullptr, nullptr, nullptr, 0);
        gemm64<2><<<dim3(Hsz / 64, SB / 64), 256>>>(
            h, g_W, g_b, gv, Hsz, Hsz, nullptr, nullptr, nullptr, 0);
        gemm64<3><<<dim3(Hsz / 64, SB / 64), 256>>>(
            a1, f_W2, f_b2, h, Hsz, Hsz, h, gv, noise, t);
    }

    // ---- decoder + output projection ----
    for (int f = 0; f < Fsz; f++) {
        gemm64<0><<<dim3(G3H / 64, SB / 64), 256>>>(
            h, dec_Whh, dec_bhh, gh, Hsz, G3H, nullptr, nullptr, nullptr, 0);
        gru_combine<true><<<(SB * Hsz + 255) / 256, 256>>>(dec_bih, gh, h, SB);
        outproj<<<SB / 8, 256>>>(h, out_W, out_b, out, f);
    }
}

// round 12
// speedup vs baseline: 1.9478x; 1.9422x over previous
#include <cuda_runtime.h>
#include <cuda_bf16.h>
#include <cstdint>

#define Bsz 128
#define Isz 32
#define Lsz 96
#define Hsz 512
#define Fsz 24
#define NSTEPS 23
#define SB 2048
#define G3H 1536
#define LB  (Lsz*Bsz)

// ---------------- scratch ----------------
__device__ __align__(16) float g_gi[(size_t)LB * G3H];
__device__ __align__(16) float g_gh[(size_t)SB * G3H];
__device__ __align__(16) float g_hA[Bsz * Hsz];
__device__ __align__(16) float g_h[SB * Hsz];
__device__ __align__(16) float g_gv[SB * Hsz];

__device__ __align__(16) __nv_bfloat16 g_xs_hi[LB * Isz],   g_xs_lo[LB * Isz];
__device__ __align__(16) __nv_bfloat16 g_hA_hi[Bsz * Hsz],  g_hA_lo[Bsz * Hsz];
__device__ __align__(16) __nv_bfloat16 g_h_hi[SB * Hsz],    g_h_lo[SB * Hsz];
__device__ __align__(16) __nv_bfloat16 g_a1_hi[SB * Hsz],   g_a1_lo[SB * Hsz];
__device__ __align__(16) __nv_bfloat16 g_wih_hi[G3H * Isz], g_wih_lo[G3H * Isz];
__device__ __align__(16) __nv_bfloat16 g_whh_hi[G3H * Hsz], g_whh_lo[G3H * Hsz];
__device__ __align__(16) __nv_bfloat16 g_fw1_hi[Hsz * Hsz], g_fw1_lo[Hsz * Hsz];
__device__ __align__(16) __nv_bfloat16 g_fw2_hi[Hsz * Hsz], g_fw2_lo[Hsz * Hsz];
__device__ __align__(16) __nv_bfloat16 g_gw_hi[Hsz * Hsz],  g_gw_lo[Hsz * Hsz];
__device__ __align__(16) __nv_bfloat16 g_dwhh_hi[G3H * Hsz],g_dwhh_lo[G3H * Hsz];

// ---------------- helpers ----------------
static __device__ __forceinline__ uint32_t smem_u32(const void* p) {
    uint32_t a;
    asm("{ .reg .u64 t; cvta.to.shared.u64 t, %1; cvt.u32.u64 %0, t; }" : "=r"(a) : "l"(p));
    return a;
}
static __device__ __forceinline__ void cp16(uint32_t dst, const void* src) {
    asm volatile("cp.async.cg.shared.global [%0], [%1], 16;" :: "r"(dst), "l"(src));
}
static __device__ __forceinline__ void cp_commit() {
    asm volatile("cp.async.commit_group;");
}
static __device__ __forceinline__ void cp_wait0() {
    asm volatile("cp.async.wait_group 0;" ::: "memory");
}
static __device__ __forceinline__ void cp_wait1() {
    asm volatile("cp.async.wait_group 1;" ::: "memory");
}
static __device__ __forceinline__ void ldm4(uint32_t& r0, uint32_t& r1, uint32_t& r2,
                                            uint32_t& r3, uint32_t a) {
    asm volatile("ldmatrix.sync.aligned.m8n8.x4.shared.b16 {%0,%1,%2,%3}, [%4];"
                 : "=r"(r0), "=r"(r1), "=r"(r2), "=r"(r3) : "r"(a));
}
static __device__ __forceinline__ void mma16816(float* c, const uint32_t* a,
                                                const uint32_t* b) {
    asm volatile(
        "mma.sync.aligned.m16n8k16.row.col.f32.bf16.bf16.f32 "
        "{%0,%1,%2,%3}, {%4,%5,%6,%7}, {%8,%9}, {%0,%1,%2,%3};"
        : "+f"(c[0]), "+f"(c[1]), "+f"(c[2]), "+f"(c[3])
        : "r"(a[0]), "r"(a[1]), "r"(a[2]), "r"(a[3]), "r"(b[0]), "r"(b[1]));
}
static __device__ __forceinline__ void split2(float v, __nv_bfloat16& hi, __nv_bfloat16& lo) {
    hi = __float2bfloat16_rn(v);
    lo = __float2bfloat16_rn(v - __bfloat162float(hi));
}

// ---------------- elementwise kernels ----------------
__global__ __launch_bounds__(256) void zero3(float* h, __nv_bfloat16* hi, __nv_bfloat16* lo, int n) {
    int i = blockIdx.x * blockDim.x + threadIdx.x;
    if (i < n) { h[i] = 0.f; hi[i] = __float2bfloat16(0.f); lo[i] = __float2bfloat16(0.f); }
}
__global__ __launch_bounds__(256) void wsplit(const float* __restrict__ s,
                                              __nv_bfloat16* __restrict__ hi,
                                              __nv_bfloat16* __restrict__ lo, int n) {
    int i = blockIdx.x * blockDim.x + threadIdx.x;
    if (i < n) { __nv_bfloat16 a, b; split2(s[i], a, b); hi[i] = a; lo[i] = b; }
}
// xs[(l*B+b)*32 + i] = x[(b*I+i)*L + l]
__global__ __launch_bounds__(256) void transpose_x(const float* __restrict__ x,
                                                   __nv_bfloat16* __restrict__ hi,
                                                   __nv_bfloat16* __restrict__ lo) {
    int o = blockIdx.x * blockDim.x + threadIdx.x;
    if (o >= LB * Isz) return;
    int i = o & 31, b = (o >> 5) & 127, l = o >> 12;
    __nv_bfloat16 a, c; split2(x[(b * Isz + i) * Lsz + l], a, c);
    hi[o] = a; lo[o] = c;
}
__global__ __launch_bounds__(256) void bcast_kernel(const float* __restrict__ src,
                                                    float* __restrict__ dst,
                                                    __nv_bfloat16* __restrict__ hi,
                                                    __nv_bfloat16* __restrict__ lo) {
    int idx = blockIdx.x * blockDim.x + threadIdx.x;
    if (idx >= SB * Hsz) return;
    float v = src[idx & (Bsz * Hsz - 1)];
    __nv_bfloat16 a, b; split2(v, a, b);
    dst[idx] = v; hi[idx] = a; lo[idx] = b;
}
template <bool GIVEC>
__global__ __launch_bounds__(256) void gru_combine(const float* __restrict__ gi,
                                                   const float* __restrict__ gh,
                                                   float* __restrict__ h,
                                                   __nv_bfloat16* __restrict__ hhi,
                                                   __nv_bfloat16* __restrict__ hlo, int M) {
    int idx = blockIdx.x * blockDim.x + threadIdx.x;
    if (idx >= M * Hsz) return;
    int m = idx >> 9, j = idx & 511;
    float gir, giz, gin;
    if (GIVEC) { gir = gi[j]; giz = gi[Hsz + j]; gin = gi[2 * Hsz + j]; }
    else {
        const float* p = gi + (size_t)m * G3H;
        gir = p[j]; giz = p[Hsz + j]; gin = p[2 * Hsz + j];
    }
    const float* q = gh + (size_t)m * G3H;
    float r = 1.f / (1.f + expf(-(gir + q[j])));
    float z = 1.f / (1.f + expf(-(giz + q[Hsz + j])));
    float n = tanhf(gin + r * q[2 * Hsz + j]);
    float v = (1.f - z) * n + z * h[idx];
    h[idx] = v;
    __nv_bfloat16 a, b; split2(v, a, b); hhi[idx] = a; hlo[idx] = b;
}
__global__ __launch_bounds__(256) void outproj(const float* __restrict__ h,
                                               const float* __restrict__ W,
                                               const float* __restrict__ bias,
                                               float* __restrict__ out, int f) {
    __shared__ float hs[8][Hsz];
    __shared__ float Ws[64][33];
    const int tid = threadIdx.x;
    const int m0 = blockIdx.x * 8;
    for (int idx = tid; idx < 8 * Hsz; idx += 256)
        hs[idx >> 9][idx & 511] = h[(size_t)(m0 + (idx >> 9)) * Hsz + (idx & 511)];
    const int r = tid >> 5, i = tid & 31;
    float acc = 0.f;
    for (int k0 = 0; k0 < Hsz; k0 += 64) {
        __syncthreads();
#pragma unroll
        for (int q = 0; q < 2; q++) {
            int fid = tid + q * 256;
            int i_ld = fid >> 4, c = fid & 15;
            float4 wv = *(const float4*)(W + (size_t)i_ld * Hsz + k0 + c * 4);
            Ws[c * 4 + 0][i_ld] = wv.x; Ws[c * 4 + 1][i_ld] = wv.y;
            Ws[c * 4 + 2][i_ld] = wv.z; Ws[c * 4 + 3][i_ld] = wv.w;
        }
        __syncthreads();
#pragma unroll 16
        for (int kk = 0; kk < 64; kk++) acc += hs[r][k0 + kk] * Ws[kk][i];
    }
    out[((size_t)(m0 + r) * Isz + i) * Fsz + f] = acc + bias[i];
}

// ---------------- bf16x2-split mma.sync GEMM ----------------
// C[M,N] = epi(A @ W^T + bias); A=(a_hi+a_lo) [M,K], W=(w_hi+w_lo) [N,K].
// CTA: 128x64, 8 warps of 32x32. K chunks of 32, cp.async double-buffered.
// SMEM rows padded to 40 bf16 (80 B) -> conflict-free ldmatrix.
// Per buffer (bytes): Ah 10240 | Al 10240 | Bh 5120 | Bl 5120 = 30720. x2 = 61440.
#define ROWB 80
#define BUF_B 30720
#define SMEM_DYN (2 * BUF_B)

template <int MODE>
__global__ __launch_bounds__(256) void gemm_tc(
    const __nv_bfloat16* __restrict__ a_hi, const __nv_bfloat16* __restrict__ a_lo,
    const __nv_bfloat16* __restrict__ w_hi, const __nv_bfloat16* __restrict__ w_lo,
    const float* __restrict__ bias, int K, int N,
    float* __restrict__ C, __nv_bfloat16* __restrict__ chi, __nv_bfloat16* __restrict__ clo,
    const float* __restrict__ hb, const float* __restrict__ gvp,
    const float* __restrict__ nz, int t)
{
    extern __shared__ __align__(16) __nv_bfloat16 sm[];
    const uint32_t sbase = smem_u32(sm);
    const int tid = threadIdx.x;
    const int lane = tid & 31, wid = tid >> 5;
    const int wm = wid >> 1, wn = wid & 1;
    const int bm = blockIdx.y * 128, bn = blockIdx.x * 64;
    const int NC = K >> 5;

    float acc[2][4][4];
#pragma unroll
    for (int a = 0; a < 2; a++)
#pragma unroll
        for (int b = 0; b < 4; b++)
#pragma unroll
            for (int c = 0; c < 4; c++) acc[a][b][c] = 0.f;

    const int arow = tid >> 2, akb = tid & 3;

    auto load_chunk = [&](int c) {
        const uint32_t base = sbase + (c & 1) * BUF_B;
        const int koff = c << 5;
#pragma unroll
        for (int u = 0; u < 2; u++) {
            int row = arow + u * 64;
            uint32_t d = base + row * ROWB + akb * 16;
            size_t go = (size_t)(bm + row) * K + koff + akb * 8;
            cp16(d, a_hi + go);
            cp16(d + 10240, a_lo + go);
        }
        {
            uint32_t d = base + 20480 + arow * ROWB + akb * 16;
            size_t go = (size_t)(bn + arow) * K + koff + akb * 8;
            cp16(d, w_hi + go);
            cp16(d + 5120, w_lo + go);
        }
        cp_commit();
    };

    load_chunk(0);
    for (int c = 0; c < NC; c++) {
        if (c + 1 < NC) { load_chunk(c + 1); cp_wait1(); }
        else cp_wait0();
        __syncthreads();

        const uint32_t base = sbase + (c & 1) * BUF_B;
#pragma unroll
        for (int ks = 0; ks < 2; ks++) {
            uint32_t ah[2][4], al[2][4], bh[4][2], bl[4][2];
#pragma unroll
            for (int mf = 0; mf < 2; mf++) {
                uint32_t ad = base + (wm * 32 + mf * 16 + (lane & 15)) * ROWB
                              + (ks * 16 + (lane >> 4) * 8) * 2;
                ldm4(ah[mf][0], ah[mf][1], ah[mf][2], ah[mf][3], ad);
                ldm4(al[mf][0], al[mf][1], al[mf][2], al[mf][3], ad + 10240);
            }
            {
                int g = lane >> 3, r = lane & 7;
#pragma unroll
                for (int nf2 = 0; nf2 < 2; nf2++) {
                    uint32_t bd = base + 20480
                                  + (wn * 32 + nf2 * 16 + (g >> 1) * 8 + r) * ROWB
                                  + (ks * 16 + (g & 1) * 8) * 2;
                    uint32_t r0, r1, r2, r3;
                    ldm4(r0, r1, r2, r3, bd);
                    bh[nf2 * 2 + 0][0] = r0; bh[nf2 * 2 + 0][1] = r1;
                    bh[nf2 * 2 + 1][0] = r2; bh[nf2 * 2 + 1][1] = r3;
                    ldm4(r0, r1, r2, r3, bd + 5120);
                    bl[nf2 * 2 + 0][0] = r0; bl[nf2 * 2 + 0][1] = r1;
                    bl[nf2 * 2 + 1][0] = r2; bl[nf2 * 2 + 1][1] = r3;
                }
            }
#pragma unroll
            for (int mf = 0; mf < 2; mf++)
#pragma unroll
                for (int nb = 0; nb < 4; nb++) {
                    mma16816(acc[mf][nb], ah[mf], bh[nb]);
                    mma16816(acc[mf][nb], ah[mf], bl[nb]);
                    mma16816(acc[mf][nb], al[mf], bh[nb]);
                }
        }
        __syncthreads();
    }

    // ---- epilogue ----
    const int gid = lane >> 2, t4 = lane & 3;
    const float dtv = 24.0f / 23.0f;
    const float sq  = 1.0214598f;  // sqrt(24/23)
#pragma unroll
    for (int mf = 0; mf < 2; mf++)
#pragma unroll
        for (int nb = 0; nb < 4; nb++) {
            const int n = bn + wn * 32 + nb * 8 + t4 * 2;
            const float b0 = bias[n], b1 = bias[n + 1];
#pragma unroll
            for (int hf = 0; hf < 2; hf++) {
                const int m = bm + wm * 32 + mf * 16 + gid + hf * 8;
                float v0 = acc[mf][nb][hf * 2 + 0] + b0;
                float v1 = acc[mf][nb][hf * 2 + 1] + b1;
                const size_t ci = (size_t)m * N + n;
                if (MODE == 1) { v0 = tanhf(v0); v1 = tanhf(v1); }
                else if (MODE == 2) {
                    v0 = (v0 > 0.f) ? v0 + log1pf(expf(-v0)) : log1pf(expf(v0));
                    v1 = (v1 > 0.f) ? v1 + log1pf(expf(-v1)) : log1pf(expf(v1));
                } else if (MODE == 3) {
                    int s = m >> 7, bb = m & 127;
                    const float* np = nz + (((size_t)s * NSTEPS + t) * Bsz + bb) * Hsz + n;
                    float2 dw = *(const float2*)np;
                    float2 hv = *(const float2*)(hb + ci);
                    float2 gg = *(const float2*)(gvp + ci);
                    v0 = hv.x + dtv * v0 + gg.x * dw.x * sq;
                    v1 = hv.y + dtv * v1 + gg.y * dw.y * sq;
                }
                if (C) *(float2*)(C + ci) = make_float2(v0, v1);
                if (chi) {
                    __nv_bfloat16 h0, l0, h1, l1;
                    split2(v0, h0, l0); split2(v1, h1, l1);
                    *(__nv_bfloat162*)(chi + ci) = __nv_bfloat162(h0, h1);
                    *(__nv_bfloat162*)(clo + ci) = __nv_bfloat162(l0, l1);
                }
            }
        }
}

// ---------------- launcher ----------------
extern "C" void kernel_launch(void* const* d_in, const int* in_sizes, int n_in,
                              void* d_out, int out_size) {
    const float* x        = (const float*)d_in[0];
    const float* noise    = (const float*)d_in[1];
    const float* enc_Wih  = (const float*)d_in[2];
    const float* enc_Whh  = (const float*)d_in[3];
    const float* enc_bih  = (const float*)d_in[4];
    const float* enc_bhh  = (const float*)d_in[5];
    const float* f_W1     = (const float*)d_in[6];
    const float* f_b1     = (const float*)d_in[7];
    const float* f_W2     = (const float*)d_in[8];
    const float* f_b2     = (const float*)d_in[9];
    const float* g_W      = (const float*)d_in[10];
    const float* g_b      = (const float*)d_in[11];
    const float* dec_Whh  = (const float*)d_in[13];
    const float* dec_bih  = (const float*)d_in[14];
    const float* dec_bhh  = (const float*)d_in[15];
    const float* out_W    = (const float*)d_in[16];
    const float* out_b    = (const float*)d_in[17];
    float* out = (float*)d_out;

    cudaFuncSetAttribute(gemm_tc<0>, cudaFuncAttributeMaxDynamicSharedMemorySize, SMEM_DYN);
    cudaFuncSetAttribute(gemm_tc<1>, cudaFuncAttributeMaxDynamicSharedMemorySize, SMEM_DYN);
    cudaFuncSetAttribute(gemm_tc<2>, cudaFuncAttributeMaxDynamicSharedMemorySize, SMEM_DYN);
    cudaFuncSetAttribute(gemm_tc<3>, cudaFuncAttributeMaxDynamicSharedMemorySize, SMEM_DYN);

    float *gi, *gh, *hA, *h, *gv;
    cudaGetSymbolAddress((void**)&gi, g_gi);
    cudaGetSymbolAddress((void**)&gh, g_gh);
    cudaGetSymbolAddress((void**)&hA, g_hA);
    cudaGetSymbolAddress((void**)&h,  g_h);
    cudaGetSymbolAddress((void**)&gv, g_gv);
    __nv_bfloat16 *xsh,*xsl,*hAh,*hAl,*hh,*hl,*a1h,*a1l,*wihh,*wihl,*whhh,*whhl,
                  *f1h,*f1l,*f2h,*f2l,*gwh,*gwl,*dwh,*dwl;
    cudaGetSymbolAddress((void**)&xsh, g_xs_hi);  cudaGetSymbolAddress((void**)&xsl, g_xs_lo);
    cudaGetSymbolAddress((void**)&hAh, g_hA_hi);  cudaGetSymbolAddress((void**)&hAl, g_hA_lo);
    cudaGetSymbolAddress((void**)&hh,  g_h_hi);   cudaGetSymbolAddress((void**)&hl,  g_h_lo);
    cudaGetSymbolAddress((void**)&a1h, g_a1_hi);  cudaGetSymbolAddress((void**)&a1l, g_a1_lo);
    cudaGetSymbolAddress((void**)&wihh,g_wih_hi); cudaGetSymbolAddress((void**)&wihl,g_wih_lo);
    cudaGetSymbolAddress((void**)&whhh,g_whh_hi); cudaGetSymbolAddress((void**)&whhl,g_whh_lo);
    cudaGetSymbolAddress((void**)&f1h, g_fw1_hi); cudaGetSymbolAddress((void**)&f1l, g_fw1_lo);
    cudaGetSymbolAddress((void**)&f2h, g_fw2_hi); cudaGetSymbolAddress((void**)&f2l, g_fw2_lo);
    cudaGetSymbolAddress((void**)&gwh, g_gw_hi);  cudaGetSymbolAddress((void**)&gwl, g_gw_lo);
    cudaGetSymbolAddress((void**)&dwh, g_dwhh_hi);cudaGetSymbolAddress((void**)&dwl, g_dwhh_lo);

    // ---- prep: split weights / inputs ----
    wsplit<<<(G3H * Isz + 255) / 256, 256>>>(enc_Wih, wihh, wihl, G3H * Isz);
    wsplit<<<(G3H * Hsz + 255) / 256, 256>>>(enc_Whh, whhh, whhl, G3H * Hsz);
    wsplit<<<(Hsz * Hsz + 255) / 256, 256>>>(f_W1, f1h, f1l, Hsz * Hsz);
    wsplit<<<(Hsz * Hsz + 255) / 256, 256>>>(f_W2, f2h, f2l, Hsz * Hsz);
    wsplit<<<(Hsz * Hsz + 255) / 256, 256>>>(g_W, gwh, gwl, Hsz * Hsz);
    wsplit<<<(G3H * Hsz + 255) / 256, 256>>>(dec_Whh, dwh, dwl, G3H * Hsz);
    transpose_x<<<(LB * Isz + 255) / 256, 256>>>(x, xsh, xsl);
    zero3<<<(Bsz * Hsz + 255) / 256, 256>>>(hA, hAh, hAl, Bsz * Hsz);

    // ---- encoder input gates: gi = xs @ Wih^T + bih  [12288 x 1536], K=32 ----
    gemm_tc<0><<<dim3(G3H / 64, LB / 128), 256, SMEM_DYN>>>(
        xsh, xsl, wihh, wihl, enc_bih, Isz, G3H, gi, nullptr, nullptr,
        nullptr, nullptr, nullptr, 0);

    // ---- encoder recurrence (M=128) ----
    for (int l = 0; l < Lsz; l++) {
        gemm_tc<0><<<dim3(G3H / 64, 1), 256, SMEM_DYN>>>(
            hAh, hAl, whhh, whhl, enc_bhh, Hsz, G3H, gh, nullptr, nullptr,
            nullptr, nullptr, nullptr, 0);
        gru_combine<false><<<(Bsz * Hsz + 255) / 256, 256>>>(
            gi + (size_t)l * Bsz * G3H, gh, hA, hAh, hAl, Bsz);
    }

    bcast_kernel<<<(SB * Hsz + 255) / 256, 256>>>(hA, h, hh, hl);

    // ---- Euler-Maruyama SDE ----
    for (int t = 0; t < NSTEPS; t++) {
        gemm_tc<1><<<dim3(Hsz / 64, SB / 128), 256, SMEM_DYN>>>(
            hh, hl, f1h, f1l, f_b1, Hsz, Hsz, nullptr, a1h, a1l,
            nullptr, nullptr, nullptr, 0);
        gemm_tc<2><<<dim3(Hsz / 64, SB / 128), 256, SMEM_DYN>>>(
            hh, hl, gwh, gwl, g_b, Hsz, Hsz, gv, nullptr, nullptr,
            nullptr, nullptr, nullptr, 0);
        gemm_tc<3><<<dim3(Hsz / 64, SB / 128), 256, SMEM_DYN>>>(
            a1h, a1l, f2h, f2l, f_b2, Hsz, Hsz, h, hh, hl,
            h, gv, noise, t);
    }

    // ---- decoder + output projection ----
    for (int f = 0; f < Fsz; f++) {
        gemm_tc<0><<<dim3(G3H / 64, SB / 128), 256, SMEM_DYN>>>(
            hh, hl, dwh, dwl, dec_bhh, Hsz, G3H, gh, nullptr, nullptr,
            nullptr, nullptr, nullptr, 0);
        gru_combine<true><<<(SB * Hsz + 255) / 256, 256>>>(dec_bih, gh, h, hh, hl, SB);
        outproj<<<SB / 8, 256>>>(h, out_W, out_b, out, f);
    }
}